// round 4
// baseline (speedup 1.0000x reference)
#include <cuda_runtime.h>

// SSIM loss, fused separable 11x11 gaussian blur + ssim map + mean reduce.
// Input: img1, img2 : [32,3,512,512] fp32. Output: scalar fp32.
// R4: fix R3 compile error — gaussian weights via __device__ constexpr
// switch-of-literals (no array object can exist -> guaranteed FFMA-immediate).
// Keep 4 z-chunk launches so ncu -s 5 profiles ssim_main.

#define IMG      512
#define TILE_W   64
#define TILE_H   32
#define HALO     5
#define IN_W     74          // TILE_W + 2*HALO
#define IN_WP    76          // padded row stride (16B aligned rows)
#define IN_H     42          // TILE_H + 2*HALO
#define NTHREADS 256
#define HPLANE   (IN_H * TILE_W)   // 2688 floats per blurred field

#define GRID_X   (IMG / TILE_W)    // 8
#define GRID_Y   (IMG / TILE_H)    // 16
#define PLANES   96
#define ZCHUNK   24                // planes per launch (4 launches)
#define NBLOCKS  (GRID_X * GRID_Y * PLANES)  // 12288

// smem: 2 raw tiles (IN_H*IN_WP each) + 5 horizontally-blurred fields
#define SMEM_FLOATS (2 * IN_H * IN_WP + 5 * HPLANE)
#define SMEM_BYTES  (SMEM_FLOATS * 4)

__device__ float g_part[NBLOCKS];

// 1D gaussian, sigma=1.5, K=11, normalized. Switch over literals: no array
// object exists, so constant-index calls MUST fold to immediates.
__device__ __forceinline__ constexpr float gw(int k) {
    switch (k) {
        case 0:  return 0.00102838f;
        case 1:  return 0.00759877f;
        case 2:  return 0.03600077f;
        case 3:  return 0.10936069f;
        case 4:  return 0.21300554f;
        case 5:  return 0.26601173f;
        case 6:  return 0.21300554f;
        case 7:  return 0.10936069f;
        case 8:  return 0.03600077f;
        case 9:  return 0.00759877f;
        case 10: return 0.00102838f;
    }
    return 0.0f;
}

__global__ __launch_bounds__(NTHREADS, 2)
void ssim_main(const float* __restrict__ img1, const float* __restrict__ img2,
               int z0) {
    extern __shared__ float smem[];
    float* s1 = smem;                       // raw x1 tile [IN_H][IN_WP]
    float* s2 = smem + IN_H * IN_WP;        // raw x2 tile
    float* sh = smem + 2 * IN_H * IN_WP;    // 5 fields [IN_H][TILE_W]

    const int tid = threadIdx.x;
    const int gx0 = blockIdx.x * TILE_W - HALO;
    const int gy0 = blockIdx.y * TILE_H - HALO;
    const int zz  = blockIdx.z + z0;
    const size_t pbase = (size_t)zz * (IMG * IMG);
    const float* p1 = img1 + pbase;
    const float* p2 = img2 + pbase;

    // ---- Phase 1: global -> smem, apply (v+1)*0.5, zero-pad out of bounds ----
    for (int idx = tid; idx < IN_H * IN_WP; idx += NTHREADS) {
        int r = idx / IN_WP;
        int c = idx - r * IN_WP;
        int gx = gx0 + c;
        int gy = gy0 + r;
        float v1 = 0.f, v2 = 0.f;
        if (c < IN_W && gx >= 0 && gx < IMG && gy >= 0 && gy < IMG) {
            int o = gy * IMG + gx;
            v1 = (p1[o] + 1.f) * 0.5f;
            v2 = (p2[o] + 1.f) * 0.5f;
        }
        s1[idx] = v1;
        s2[idx] = v2;
    }
    __syncthreads();

    // ---- Phase 2: horizontal 11-tap blur of 5 fields, 4 output cols / task ----
    for (int t = tid; t < IN_H * 16; t += NTHREADS) {
        int row = t >> 4;
        int c0  = (t & 15) << 2;

        float a[16], b[16];
        {
            const float4* a4 = (const float4*)(s1 + row * IN_WP + c0);
            const float4* b4 = (const float4*)(s2 + row * IN_WP + c0);
            ((float4*)a)[0] = a4[0]; ((float4*)a)[1] = a4[1];
            ((float4*)a)[2] = a4[2]; ((float4*)a)[3] = a4[3];
            ((float4*)b)[0] = b4[0]; ((float4*)b)[1] = b4[1];
            ((float4*)b)[2] = b4[2]; ((float4*)b)[3] = b4[3];
        }

        float m1[4]  = {0.f, 0.f, 0.f, 0.f};
        float m2[4]  = {0.f, 0.f, 0.f, 0.f};
        float q11[4] = {0.f, 0.f, 0.f, 0.f};
        float q22[4] = {0.f, 0.f, 0.f, 0.f};
        float q12[4] = {0.f, 0.f, 0.f, 0.f};

        #pragma unroll
        for (int i = 0; i < 14; i++) {
            float fa = a[i], fb = b[i];
            float faa = fa * fa, fbb = fb * fb, fab = fa * fb;
            #pragma unroll
            for (int j = 0; j < 4; j++) {
                int k = i - j;
                if (k >= 0 && k < 11) {
                    float w = gw(k);
                    m1[j]  = fmaf(fa,  w, m1[j]);
                    m2[j]  = fmaf(fb,  w, m2[j]);
                    q11[j] = fmaf(faa, w, q11[j]);
                    q22[j] = fmaf(fbb, w, q22[j]);
                    q12[j] = fmaf(fab, w, q12[j]);
                }
            }
        }

        float* hb = sh + row * TILE_W + c0;
        *(float4*)(hb + 0 * HPLANE) = make_float4(m1[0],  m1[1],  m1[2],  m1[3]);
        *(float4*)(hb + 1 * HPLANE) = make_float4(m2[0],  m2[1],  m2[2],  m2[3]);
        *(float4*)(hb + 2 * HPLANE) = make_float4(q11[0], q11[1], q11[2], q11[3]);
        *(float4*)(hb + 3 * HPLANE) = make_float4(q22[0], q22[1], q22[2], q22[3]);
        *(float4*)(hb + 4 * HPLANE) = make_float4(q12[0], q12[1], q12[2], q12[3]);
    }
    __syncthreads();

    // ---- Phase 3: vertical 11-tap blur + ssim, 8 output rows / thread ----
    const int col = tid & 63;
    const int r0  = (tid >> 6) << 3;   // 0,8,16,24

    float acc0[8], acc1[8], acc2[8], acc3[8], acc4[8];
    #pragma unroll
    for (int j = 0; j < 8; j++) {
        acc0[j] = 0.f; acc1[j] = 0.f; acc2[j] = 0.f; acc3[j] = 0.f; acc4[j] = 0.f;
    }

    #pragma unroll
    for (int i = 0; i < 18; i++) {
        const float* hp = sh + (r0 + i) * TILE_W + col;
        float h0 = hp[0 * HPLANE];
        float h1 = hp[1 * HPLANE];
        float h2 = hp[2 * HPLANE];
        float h3 = hp[3 * HPLANE];
        float h4 = hp[4 * HPLANE];
        #pragma unroll
        for (int j = 0; j < 8; j++) {
            int k = i - j;
            if (k >= 0 && k < 11) {
                float w = gw(k);
                acc0[j] = fmaf(h0, w, acc0[j]);
                acc1[j] = fmaf(h1, w, acc1[j]);
                acc2[j] = fmaf(h2, w, acc2[j]);
                acc3[j] = fmaf(h3, w, acc3[j]);
                acc4[j] = fmaf(h4, w, acc4[j]);
            }
        }
    }

    const float C1 = 0.0001f;   // 0.01^2
    const float C2 = 0.0009f;   // 0.03^2
    float tsum = 0.f;
    #pragma unroll
    for (int j = 0; j < 8; j++) {
        float mu1 = acc0[j], mu2 = acc1[j];
        float mu1s = mu1 * mu1, mu2s = mu2 * mu2, mu12 = mu1 * mu2;
        float sA  = acc2[j] - mu1s;
        float sB  = acc3[j] - mu2s;
        float sAB = acc4[j] - mu12;
        float num = (2.f * mu12 + C1) * (2.f * sAB + C2);
        float den = (mu1s + mu2s + C1) * (sA + sB + C2);
        tsum += __fdividef(num, den);
    }

    // ---- Reduction: warp shuffle -> block -> one STG per block ----
    #pragma unroll
    for (int off = 16; off; off >>= 1)
        tsum += __shfl_xor_sync(0xffffffffu, tsum, off);

    __syncthreads();   // smem reuse guard
    if ((tid & 31) == 0) smem[tid >> 5] = tsum;
    __syncthreads();
    if (tid == 0) {
        float bs = 0.f;
        #pragma unroll
        for (int i = 0; i < NTHREADS / 32; i++) bs += smem[i];
        int slot = (zz * GRID_Y + blockIdx.y) * GRID_X + blockIdx.x;
        g_part[slot] = bs;
    }
}

__global__ __launch_bounds__(1024)
void ssim_reduce(float* out, double inv_n) {
    __shared__ double wsum[32];
    const int tid = threadIdx.x;

    double s = 0.0;
    #pragma unroll
    for (int i = 0; i < NBLOCKS / 1024; i++)
        s += (double)g_part[tid + i * 1024];

    #pragma unroll
    for (int off = 16; off; off >>= 1)
        s += __shfl_xor_sync(0xffffffffu, s, off);

    if ((tid & 31) == 0) wsum[tid >> 5] = s;
    __syncthreads();
    if (tid == 0) {
        double t = 0.0;
        #pragma unroll
        for (int i = 0; i < 32; i++) t += wsum[i];
        out[0] = 1.0f - (float)(t * inv_n);
    }
}

extern "C" void kernel_launch(void* const* d_in, const int* in_sizes, int n_in,
                              void* d_out, int out_size) {
    const float* img1 = (const float*)d_in[0];
    const float* img2 = (const float*)d_in[1];
    (void)n_in; (void)out_size; (void)in_sizes;

    cudaFuncSetAttribute(ssim_main, cudaFuncAttributeMaxDynamicSharedMemorySize,
                         SMEM_BYTES);

    // 4 z-chunks (5 launches total per call) so ncu -s 5 -c 1 profiles ssim_main.
    dim3 grid(GRID_X, GRID_Y, ZCHUNK);
    for (int z0 = 0; z0 < PLANES; z0 += ZCHUNK)
        ssim_main<<<grid, NTHREADS, SMEM_BYTES>>>(img1, img2, z0);

    double inv_n = 1.0 / ((double)PLANES * IMG * IMG);
    ssim_reduce<<<1, 1024>>>((float*)d_out, inv_n);
}

// round 5
// speedup vs baseline: 1.6556x; 1.6556x over previous
#include <cuda_runtime.h>

// SSIM loss, fused separable 11x11 gaussian blur + ssim map + mean reduce.
// R5: retile 64x32 -> 32x32. smem 79KB -> 41.7KB -> 5 CTAs/SM (occ 24%->62%).
// Profile R4 showed issue=38.7%, fma=25.9%, occ=24.3%: latency-bound, not
// pipe-bound -> occupancy is the lever. Single main launch (no z-chunks).

#define IMG      512
#define TILE_W   32
#define TILE_H   32
#define HALO     5
#define IN_W     42          // TILE_W + 2*HALO
#define IN_WP    44          // padded row stride (16B aligned rows)
#define IN_H     42          // TILE_H + 2*HALO
#define NTHREADS 256
#define HPLANE   (IN_H * TILE_W)   // 1344 floats per blurred field

#define GRID_X   (IMG / TILE_W)    // 16
#define GRID_Y   (IMG / TILE_H)    // 16
#define PLANES   96
#define NBLOCKS  (GRID_X * GRID_Y * PLANES)  // 24576

// smem: 2 raw tiles (IN_H*IN_WP each) + 5 horizontally-blurred fields
#define SMEM_FLOATS (2 * IN_H * IN_WP + 5 * HPLANE)   // 10416
#define SMEM_BYTES  (SMEM_FLOATS * 4)                 // 41664

__device__ float g_part[NBLOCKS];

// 1D gaussian, sigma=1.5, K=11, normalized. Switch over literals: constant
// indices fold to FFMA immediates.
__device__ __forceinline__ constexpr float gw(int k) {
    switch (k) {
        case 0:  return 0.00102838f;
        case 1:  return 0.00759877f;
        case 2:  return 0.03600077f;
        case 3:  return 0.10936069f;
        case 4:  return 0.21300554f;
        case 5:  return 0.26601173f;
        case 6:  return 0.21300554f;
        case 7:  return 0.10936069f;
        case 8:  return 0.03600077f;
        case 9:  return 0.00759877f;
        case 10: return 0.00102838f;
    }
    return 0.0f;
}

__global__ __launch_bounds__(NTHREADS, 5)
void ssim_main(const float* __restrict__ img1, const float* __restrict__ img2) {
    extern __shared__ float smem[];
    float* s1 = smem;                       // raw x1 tile [IN_H][IN_WP]
    float* s2 = smem + IN_H * IN_WP;        // raw x2 tile
    float* sh = smem + 2 * IN_H * IN_WP;    // 5 fields [IN_H][TILE_W]

    const int tid = threadIdx.x;
    const int gx0 = blockIdx.x * TILE_W - HALO;
    const int gy0 = blockIdx.y * TILE_H - HALO;
    const size_t pbase = (size_t)blockIdx.z * (IMG * IMG);
    const float* p1 = img1 + pbase;
    const float* p2 = img2 + pbase;

    // ---- Phase 1: global -> smem, apply (v+1)*0.5, zero-pad out of bounds ----
    for (int idx = tid; idx < IN_H * IN_WP; idx += NTHREADS) {
        int r = idx / IN_WP;
        int c = idx - r * IN_WP;
        int gx = gx0 + c;
        int gy = gy0 + r;
        float v1 = 0.f, v2 = 0.f;
        if (c < IN_W && gx >= 0 && gx < IMG && gy >= 0 && gy < IMG) {
            int o = gy * IMG + gx;
            v1 = (p1[o] + 1.f) * 0.5f;
            v2 = (p2[o] + 1.f) * 0.5f;
        }
        s1[idx] = v1;
        s2[idx] = v2;
    }
    __syncthreads();

    // ---- Phase 2: horizontal 11-tap blur of 5 fields, 4 output cols / task ----
    // tasks: 42 rows x 8 col-groups = 336
    for (int t = tid; t < IN_H * 8; t += NTHREADS) {
        int row = t >> 3;
        int c0  = (t & 7) << 2;

        float a[16], b[16];
        {
            const float4* a4 = (const float4*)(s1 + row * IN_WP + c0);
            const float4* b4 = (const float4*)(s2 + row * IN_WP + c0);
            ((float4*)a)[0] = a4[0]; ((float4*)a)[1] = a4[1];
            ((float4*)a)[2] = a4[2]; ((float4*)a)[3] = a4[3];
            ((float4*)b)[0] = b4[0]; ((float4*)b)[1] = b4[1];
            ((float4*)b)[2] = b4[2]; ((float4*)b)[3] = b4[3];
        }

        float m1[4]  = {0.f, 0.f, 0.f, 0.f};
        float m2[4]  = {0.f, 0.f, 0.f, 0.f};
        float q11[4] = {0.f, 0.f, 0.f, 0.f};
        float q22[4] = {0.f, 0.f, 0.f, 0.f};
        float q12[4] = {0.f, 0.f, 0.f, 0.f};

        #pragma unroll
        for (int i = 0; i < 14; i++) {
            float fa = a[i], fb = b[i];
            float faa = fa * fa, fbb = fb * fb, fab = fa * fb;
            #pragma unroll
            for (int j = 0; j < 4; j++) {
                int k = i - j;
                if (k >= 0 && k < 11) {
                    float w = gw(k);
                    m1[j]  = fmaf(fa,  w, m1[j]);
                    m2[j]  = fmaf(fb,  w, m2[j]);
                    q11[j] = fmaf(faa, w, q11[j]);
                    q22[j] = fmaf(fbb, w, q22[j]);
                    q12[j] = fmaf(fab, w, q12[j]);
                }
            }
        }

        float* hb = sh + row * TILE_W + c0;
        *(float4*)(hb + 0 * HPLANE) = make_float4(m1[0],  m1[1],  m1[2],  m1[3]);
        *(float4*)(hb + 1 * HPLANE) = make_float4(m2[0],  m2[1],  m2[2],  m2[3]);
        *(float4*)(hb + 2 * HPLANE) = make_float4(q11[0], q11[1], q11[2], q11[3]);
        *(float4*)(hb + 3 * HPLANE) = make_float4(q22[0], q22[1], q22[2], q22[3]);
        *(float4*)(hb + 4 * HPLANE) = make_float4(q12[0], q12[1], q12[2], q12[3]);
    }
    __syncthreads();

    // ---- Phase 3: vertical 11-tap blur + ssim, 4 output rows / thread ----
    const int col = tid & 31;
    const int r0  = (tid >> 5) << 2;   // 0,4,...,28

    float acc0[4], acc1[4], acc2[4], acc3[4], acc4[4];
    #pragma unroll
    for (int j = 0; j < 4; j++) {
        acc0[j] = 0.f; acc1[j] = 0.f; acc2[j] = 0.f; acc3[j] = 0.f; acc4[j] = 0.f;
    }

    #pragma unroll
    for (int i = 0; i < 14; i++) {
        const float* hp = sh + (r0 + i) * TILE_W + col;
        float h0 = hp[0 * HPLANE];
        float h1 = hp[1 * HPLANE];
        float h2 = hp[2 * HPLANE];
        float h3 = hp[3 * HPLANE];
        float h4 = hp[4 * HPLANE];
        #pragma unroll
        for (int j = 0; j < 4; j++) {
            int k = i - j;
            if (k >= 0 && k < 11) {
                float w = gw(k);
                acc0[j] = fmaf(h0, w, acc0[j]);
                acc1[j] = fmaf(h1, w, acc1[j]);
                acc2[j] = fmaf(h2, w, acc2[j]);
                acc3[j] = fmaf(h3, w, acc3[j]);
                acc4[j] = fmaf(h4, w, acc4[j]);
            }
        }
    }

    const float C1 = 0.0001f;   // 0.01^2
    const float C2 = 0.0009f;   // 0.03^2
    float tsum = 0.f;
    #pragma unroll
    for (int j = 0; j < 4; j++) {
        float mu1 = acc0[j], mu2 = acc1[j];
        float mu1s = mu1 * mu1, mu2s = mu2 * mu2, mu12 = mu1 * mu2;
        float sA  = acc2[j] - mu1s;
        float sB  = acc3[j] - mu2s;
        float sAB = acc4[j] - mu12;
        float num = (2.f * mu12 + C1) * (2.f * sAB + C2);
        float den = (mu1s + mu2s + C1) * (sA + sB + C2);
        tsum += __fdividef(num, den);
    }

    // ---- Reduction: warp shuffle -> block -> one STG per block ----
    #pragma unroll
    for (int off = 16; off; off >>= 1)
        tsum += __shfl_xor_sync(0xffffffffu, tsum, off);

    __syncthreads();   // smem reuse guard
    if ((tid & 31) == 0) smem[tid >> 5] = tsum;
    __syncthreads();
    if (tid == 0) {
        float bs = 0.f;
        #pragma unroll
        for (int i = 0; i < NTHREADS / 32; i++) bs += smem[i];
        int slot = (blockIdx.z * GRID_Y + blockIdx.y) * GRID_X + blockIdx.x;
        g_part[slot] = bs;
    }
}

__global__ __launch_bounds__(1024)
void ssim_reduce(float* out, double inv_n) {
    __shared__ double wsum[32];
    const int tid = threadIdx.x;

    double s = 0.0;
    #pragma unroll
    for (int i = 0; i < NBLOCKS / 1024; i++)
        s += (double)g_part[tid + i * 1024];

    #pragma unroll
    for (int off = 16; off; off >>= 1)
        s += __shfl_xor_sync(0xffffffffu, s, off);

    if ((tid & 31) == 0) wsum[tid >> 5] = s;
    __syncthreads();
    if (tid == 0) {
        double t = 0.0;
        #pragma unroll
        for (int i = 0; i < 32; i++) t += wsum[i];
        out[0] = 1.0f - (float)(t * inv_n);
    }
}

extern "C" void kernel_launch(void* const* d_in, const int* in_sizes, int n_in,
                              void* d_out, int out_size) {
    const float* img1 = (const float*)d_in[0];
    const float* img2 = (const float*)d_in[1];
    (void)n_in; (void)out_size; (void)in_sizes;

    cudaFuncSetAttribute(ssim_main, cudaFuncAttributeMaxDynamicSharedMemorySize,
                         SMEM_BYTES);

    dim3 grid(GRID_X, GRID_Y, PLANES);
    ssim_main<<<grid, NTHREADS, SMEM_BYTES>>>(img1, img2);

    double inv_n = 1.0 / ((double)PLANES * IMG * IMG);
    ssim_reduce<<<1, 1024>>>((float*)d_out, inv_n);
}

// round 6
// speedup vs baseline: 1.7409x; 1.0515x over previous
#include <cuda_runtime.h>

// SSIM loss, fused separable 11x11 gaussian blur + ssim map + mean reduce.
// R6: tile 32x32 -> 32x22 so phase2 tasks = IN_H*8 = 256 = exactly NTHREADS
// (kills the ceil-2-pass imbalance where 69% of warps idled in pass 2).
// smem 41.7KB -> 31.7KB -> 6 CTAs/SM. 2-stage reduce replaces 20us 1-block
// reduce. Main split in 2 z-chunks so ncu -s 5 profiles it.

#define IMG      512
#define TW       32
#define TH       22
#define HALO     5
#define INW      42          // TW + 2*HALO
#define INWP     44          // padded row stride
#define INH      32          // TH + 2*HALO  (=> tasks = 32*8 = 256)
#define NT       256
#define HPLANE   (INH * TW)  // 1024 floats per blurred field

#define GX       16          // 512/32
#define GY       24          // ceil(512/22) -> 528 rows, last 16 masked
#define PL       96
#define NB       (GX * GY * PL)   // 36864 = 36*1024

#define SMEM_FLOATS (2 * INH * INWP + 5 * HPLANE)   // 7936
#define SMEM_BYTES  (SMEM_FLOATS * 4)               // 31744

__device__ float g_part[NB];
__device__ float g_part2[36];

// 1D gaussian, sigma=1.5, K=11, normalized. Constant indices fold to
// FFMA immediates (rt_SMSP=1).
__device__ __forceinline__ constexpr float gw(int k) {
    switch (k) {
        case 0:  return 0.00102838f;
        case 1:  return 0.00759877f;
        case 2:  return 0.03600077f;
        case 3:  return 0.10936069f;
        case 4:  return 0.21300554f;
        case 5:  return 0.26601173f;
        case 6:  return 0.21300554f;
        case 7:  return 0.10936069f;
        case 8:  return 0.03600077f;
        case 9:  return 0.00759877f;
        case 10: return 0.00102838f;
    }
    return 0.0f;
}

__global__ __launch_bounds__(NT, 6)
void ssim_main(const float* __restrict__ img1, const float* __restrict__ img2,
               int z0) {
    extern __shared__ float smem[];
    float* s1 = smem;                       // raw x1 tile [INH][INWP]
    float* s2 = smem + INH * INWP;          // raw x2 tile
    float* sh = smem + 2 * INH * INWP;      // 5 fields [INH][TW]

    const int tid = threadIdx.x;
    const int gx0 = blockIdx.x * TW - HALO;
    const int gy0 = blockIdx.y * TH - HALO;
    const size_t pbase = (size_t)(blockIdx.z + z0) * (IMG * IMG);
    const float* p1 = img1 + pbase;
    const float* p2 = img2 + pbase;

    // ---- Phase 1: global -> smem, (v+1)*0.5, zero-pad OOB ----
    // thread (r = tid>>3, c = tid&7) covers cols c, c+8, ..., 6 iters
    {
        const int r  = tid >> 3;
        const int c  = tid & 7;
        const int gy = gy0 + r;
        const bool rowok = (gy >= 0) && (gy < IMG);
        const float* q1 = p1 + (size_t)gy * IMG;
        const float* q2 = p2 + (size_t)gy * IMG;
        #pragma unroll
        for (int k = 0; k < 6; k++) {
            int cc = c + 8 * k;
            if (cc < INWP) {
                int gx = gx0 + cc;
                float v1 = 0.f, v2 = 0.f;
                if (rowok && cc < INW && gx >= 0 && gx < IMG) {
                    v1 = (q1[gx] + 1.f) * 0.5f;
                    v2 = (q2[gx] + 1.f) * 0.5f;
                }
                s1[r * INWP + cc] = v1;
                s2[r * INWP + cc] = v2;
            }
        }
    }
    __syncthreads();

    // ---- Phase 2: horizontal 11-tap blur, EXACTLY one task per thread ----
    {
        const int row = tid >> 3;
        const int c0  = (tid & 7) << 2;

        float a[16], b[16];
        {
            const float4* a4 = (const float4*)(s1 + row * INWP + c0);
            const float4* b4 = (const float4*)(s2 + row * INWP + c0);
            ((float4*)a)[0] = a4[0]; ((float4*)a)[1] = a4[1];
            ((float4*)a)[2] = a4[2]; ((float4*)a)[3] = a4[3];
            ((float4*)b)[0] = b4[0]; ((float4*)b)[1] = b4[1];
            ((float4*)b)[2] = b4[2]; ((float4*)b)[3] = b4[3];
        }

        float m1[4]  = {0.f, 0.f, 0.f, 0.f};
        float m2[4]  = {0.f, 0.f, 0.f, 0.f};
        float q11[4] = {0.f, 0.f, 0.f, 0.f};
        float q22[4] = {0.f, 0.f, 0.f, 0.f};
        float q12[4] = {0.f, 0.f, 0.f, 0.f};

        #pragma unroll
        for (int i = 0; i < 14; i++) {
            float fa = a[i], fb = b[i];
            float faa = fa * fa, fbb = fb * fb, fab = fa * fb;
            #pragma unroll
            for (int j = 0; j < 4; j++) {
                int k = i - j;
                if (k >= 0 && k < 11) {
                    float w = gw(k);
                    m1[j]  = fmaf(fa,  w, m1[j]);
                    m2[j]  = fmaf(fb,  w, m2[j]);
                    q11[j] = fmaf(faa, w, q11[j]);
                    q22[j] = fmaf(fbb, w, q22[j]);
                    q12[j] = fmaf(fab, w, q12[j]);
                }
            }
        }

        float* hb = sh + row * TW + c0;
        *(float4*)(hb + 0 * HPLANE) = make_float4(m1[0],  m1[1],  m1[2],  m1[3]);
        *(float4*)(hb + 1 * HPLANE) = make_float4(m2[0],  m2[1],  m2[2],  m2[3]);
        *(float4*)(hb + 2 * HPLANE) = make_float4(q11[0], q11[1], q11[2], q11[3]);
        *(float4*)(hb + 3 * HPLANE) = make_float4(q22[0], q22[1], q22[2], q22[3]);
        *(float4*)(hb + 4 * HPLANE) = make_float4(q12[0], q12[1], q12[2], q12[3]);
    }
    __syncthreads();

    // ---- Phase 3: vertical blur + ssim. 22 rows: groups 0-5 do 3 rows,
    //      groups 6-7 do 2 rows (3rd computed but masked). ----
    const int col = tid & 31;
    const int g   = tid >> 5;
    const int r_start = (g < 6) ? 3 * g : 18 + 2 * (g - 6);

    float acc0[3], acc1[3], acc2[3], acc3[3], acc4[3];
    #pragma unroll
    for (int j = 0; j < 3; j++) {
        acc0[j] = 0.f; acc1[j] = 0.f; acc2[j] = 0.f; acc3[j] = 0.f; acc4[j] = 0.f;
    }

    #pragma unroll
    for (int i = 0; i < 13; i++) {
        int ri = r_start + i;
        if (ri > INH - 1) ri = INH - 1;   // clamp: only dead lanes hit this
        const float* hp = sh + ri * TW + col;
        float h0 = hp[0 * HPLANE];
        float h1 = hp[1 * HPLANE];
        float h2 = hp[2 * HPLANE];
        float h3 = hp[3 * HPLANE];
        float h4 = hp[4 * HPLANE];
        #pragma unroll
        for (int j = 0; j < 3; j++) {
            int k = i - j;
            if (k >= 0 && k < 11) {
                float w = gw(k);
                acc0[j] = fmaf(h0, w, acc0[j]);
                acc1[j] = fmaf(h1, w, acc1[j]);
                acc2[j] = fmaf(h2, w, acc2[j]);
                acc3[j] = fmaf(h3, w, acc3[j]);
                acc4[j] = fmaf(h4, w, acc4[j]);
            }
        }
    }

    const float C1 = 0.0001f;   // 0.01^2
    const float C2 = 0.0009f;   // 0.03^2
    const int   gyb = blockIdx.y * TH + r_start;
    float tsum = 0.f;
    #pragma unroll
    for (int j = 0; j < 3; j++) {
        bool valid = (j < 2 || g < 6) && (gyb + j < IMG);
        if (valid) {
            float mu1 = acc0[j], mu2 = acc1[j];
            float mu1s = mu1 * mu1, mu2s = mu2 * mu2, mu12 = mu1 * mu2;
            float sA  = acc2[j] - mu1s;
            float sB  = acc3[j] - mu2s;
            float sAB = acc4[j] - mu12;
            float num = (2.f * mu12 + C1) * (2.f * sAB + C2);
            float den = (mu1s + mu2s + C1) * (sA + sB + C2);
            tsum += __fdividef(num, den);
        }
    }

    // ---- Reduction: warp shuffle -> block -> one STG per block ----
    #pragma unroll
    for (int off = 16; off; off >>= 1)
        tsum += __shfl_xor_sync(0xffffffffu, tsum, off);

    __syncthreads();   // all reads of sh done before smem reuse
    if ((tid & 31) == 0) smem[tid >> 5] = tsum;
    __syncthreads();
    if (tid == 0) {
        float bs = 0.f;
        #pragma unroll
        for (int i = 0; i < NT / 32; i++) bs += smem[i];
        int slot = ((blockIdx.z + z0) * GY + blockIdx.y) * GX + blockIdx.x;
        g_part[slot] = bs;
    }
}

__global__ __launch_bounds__(1024)
void ssim_reduce1() {
    __shared__ float wsum[32];
    const int tid = threadIdx.x;
    float s = g_part[blockIdx.x * 1024 + tid];

    #pragma unroll
    for (int off = 16; off; off >>= 1)
        s += __shfl_xor_sync(0xffffffffu, s, off);
    if ((tid & 31) == 0) wsum[tid >> 5] = s;
    __syncthreads();
    if (tid < 32) {
        float t = wsum[tid];
        #pragma unroll
        for (int off = 16; off; off >>= 1)
            t += __shfl_xor_sync(0xffffffffu, t, off);
        if (tid == 0) g_part2[blockIdx.x] = t;
    }
}

__global__ void ssim_fin(float* out, double inv_n) {
    const int tid = threadIdx.x;   // 32 threads
    double s = (double)g_part2[tid];
    if (tid < 4) s += (double)g_part2[tid + 32];
    #pragma unroll
    for (int off = 16; off; off >>= 1)
        s += __shfl_xor_sync(0xffffffffu, s, off);
    if (tid == 0) out[0] = 1.0f - (float)(s * inv_n);
}

extern "C" void kernel_launch(void* const* d_in, const int* in_sizes, int n_in,
                              void* d_out, int out_size) {
    const float* img1 = (const float*)d_in[0];
    const float* img2 = (const float*)d_in[1];
    (void)n_in; (void)out_size; (void)in_sizes;

    cudaFuncSetAttribute(ssim_main, cudaFuncAttributeMaxDynamicSharedMemorySize,
                         SMEM_BYTES);

    // 2 z-chunks (4 launches/call) so ncu -s 5 -c 1 profiles ssim_main.
    dim3 grid(GX, GY, PL / 2);
    ssim_main<<<grid, NT, SMEM_BYTES>>>(img1, img2, 0);
    ssim_main<<<grid, NT, SMEM_BYTES>>>(img1, img2, PL / 2);

    ssim_reduce1<<<36, 1024>>>();
    double inv_n = 1.0 / ((double)PL * IMG * IMG);
    ssim_fin<<<1, 32>>>((float*)d_out, inv_n);
}